// round 14
// baseline (speedup 1.0000x reference)
#include <cuda_runtime.h>
#include <cuda_bf16.h>
#include <cstdint>

#define NUM_NODES 10000
#define N_EDGES   640000
#define D         128
#define BUCKET    128
#define OVF_MAX   4096

// ---------------- device scratch ----------------
__device__ float d_S[NUM_NODES * D];
__device__ float d_A[NUM_NODES * D];
__device__ int   d_cur[NUM_NODES];
__device__ float d_degf[NUM_NODES];
__device__ int2  d_perm2[NUM_NODES * BUCKET];
__device__ int3  d_ovf[OVF_MAX];
__device__ int   d_ovf_cnt;
__device__ __nv_bfloat16 d_MThi[128 * 512];
__device__ __nv_bfloat16 d_MTlo[128 * 512];
__device__ float d_cvec[D];
__device__ int   d_is64;

// ---------------- helpers ----------------
__device__ __forceinline__ int load_idx(const void* ei, int which, int e, int is64) {
    if (is64) {
        const long long* p = (const long long*)ei;
        return (int)__ldg(p + (size_t)which * N_EDGES + e);
    } else {
        const int* p = (const int*)ei;
        return __ldg(p + (size_t)which * N_EDGES + e);
    }
}
__device__ __forceinline__ float4 ldg4(const float* p)  { return __ldg((const float4*)p); }
__device__ __forceinline__ float4 ldcs4(const float* p) { return __ldcs((const float4*)p); }

__device__ __forceinline__ uint32_t smem_u32(const void* p) {
    uint32_t a;
    asm("{ .reg .u64 t; cvta.to.shared.u64 t, %1; cvt.u32.u64 %0, t; }" : "=r"(a) : "l"(p));
    return a;
}

__device__ __forceinline__ void split2(float a, float b, uint32_t& hi, uint32_t& lo) {
    __nv_bfloat162 h = __floats2bfloat162_rn(a, b);
    float2 hf = __bfloat1622float2(h);
    __nv_bfloat162 l = __floats2bfloat162_rn(a - hf.x, b - hf.y);
    hi = *reinterpret_cast<uint32_t*>(&h);
    lo = *reinterpret_cast<uint32_t*>(&l);
}

__device__ __forceinline__ void ldm_x4(uint32_t& r0, uint32_t& r1, uint32_t& r2, uint32_t& r3,
                                       uint32_t addr) {
    asm volatile("ldmatrix.sync.aligned.m8n8.x4.shared.b16 {%0,%1,%2,%3}, [%4];"
                 : "=r"(r0), "=r"(r1), "=r"(r2), "=r"(r3) : "r"(addr));
}
__device__ __forceinline__ void mma16816(float* c,
                                         uint32_t a0, uint32_t a1, uint32_t a2, uint32_t a3,
                                         uint32_t b0, uint32_t b1) {
    asm volatile(
        "mma.sync.aligned.m16n8k16.row.col.f32.bf16.bf16.f32 "
        "{%0,%1,%2,%3}, {%4,%5,%6,%7}, {%8,%9}, {%0,%1,%2,%3};"
        : "+f"(c[0]), "+f"(c[1]), "+f"(c[2]), "+f"(c[3])
        : "r"(a0), "r"(a1), "r"(a2), "r"(a3), "r"(b0), "r"(b1));
}

// ---------------- K0: setup ----------------
__global__ void k_setup(const float* __restrict__ W1,
                        const float* __restrict__ b1,
                        const float* __restrict__ W2,
                        const int*   __restrict__ ei_words) {
    int r = blockIdx.x, o = threadIdx.x;
    if (r >= 512) {
        if (r == 512) {
            int w = ei_words[2 * o + 1];
            int any = __syncthreads_or(w != 0);
            if (o == 0) { d_is64 = (any == 0) ? 1 : 0; d_ovf_cnt = 0; }
        } else {
            int i = (r - 513) * 128 + o;
            if (i < NUM_NODES) d_cur[i] = 0;
        }
        return;
    }
    __shared__ float row[D];
    float v;
    if (r >= 256 && r < 384) {
        v = W2[(128 + (r - 256)) * D + o];
    } else {
        int w1row = (r < 128) ? r : (r < 256) ? (256 + (r - 128)) : (128 + (r - 384));
        row[o] = W1[w1row * D + o];
        __syncthreads();
        float acc = 0.f;
#pragma unroll 8
        for (int h = 0; h < D; h++) acc += row[h] * __ldg(W2 + h * D + o);
        v = acc;
        if (r == 0) {
            __syncthreads();
            row[o] = b1[o];
            __syncthreads();
            float c = 0.f;
#pragma unroll 8
            for (int h = 0; h < D; h++) c += row[h] * __ldg(W2 + h * D + o);
            d_cvec[o] = c;
        }
    }
    __nv_bfloat16 hi = __float2bfloat16_rn(v);
    d_MThi[o * 512 + r] = hi;
    d_MTlo[o * 512 + r] = __float2bfloat16_rn(v - __bfloat162float(hi));
}

// ---------------- K1: single-pass bucket scatter ----------------
__global__ void k_scatter(const void* ei) {
    int is64 = d_is64;
    int e = blockIdx.x * blockDim.x + threadIdx.x;
    if (e >= N_EDGES) return;
    int dst = load_idx(ei, 1, e, is64);
    int src = load_idx(ei, 0, e, is64);
    int pos = atomicAdd(&d_cur[dst], 1);
    if (pos < BUCKET) {
        d_perm2[(dst << 7) + pos] = make_int2(e, src);
    } else {
        int o = atomicAdd(&d_ovf_cnt, 1);
        if (o < OVF_MAX) d_ovf[o] = make_int3(dst, e, src);
    }
}

// ---------------- K2: segment sums — two warps per node (R13 known-good) ----------------
__global__ void k_agg(const float* __restrict__ x, const float* __restrict__ ea) {
    __shared__ float sS[4][128];
    __shared__ float sA[4][128];
    int wid = threadIdx.x >> 5;
    int nl = wid >> 1;
    int half = wid & 1;
    int lane = threadIdx.x & 31;
    int n = blockIdx.x * 4 + nl;
    if (n >= NUM_NODES) return;
    int deg = d_cur[n];
    int cnt = min(deg, BUCKET);
    const int2* bucket = d_perm2 + ((size_t)n << 7);

    float4 aS = make_float4(0.f, 0.f, 0.f, 0.f);
    float4 aA = make_float4(0.f, 0.f, 0.f, 0.f);

    int groups = cnt >> 2;
    for (int g = half; g < groups; g += 2) {
        int j = g * 4;
        int2 p0 = __ldg(bucket + j + 0);
        int2 p1 = __ldg(bucket + j + 1);
        int2 p2 = __ldg(bucket + j + 2);
        int2 p3 = __ldg(bucket + j + 3);
        float4 x0 = ldg4(x + (size_t)p0.y * D + lane * 4);
        float4 x1 = ldg4(x + (size_t)p1.y * D + lane * 4);
        float4 x2 = ldg4(x + (size_t)p2.y * D + lane * 4);
        float4 x3 = ldg4(x + (size_t)p3.y * D + lane * 4);
        float4 a0 = ldcs4(ea + (size_t)p0.x * D + lane * 4);
        float4 a1 = ldcs4(ea + (size_t)p1.x * D + lane * 4);
        float4 a2 = ldcs4(ea + (size_t)p2.x * D + lane * 4);
        float4 a3 = ldcs4(ea + (size_t)p3.x * D + lane * 4);
        aS.x += (x0.x + x1.x) + (x2.x + x3.x);
        aS.y += (x0.y + x1.y) + (x2.y + x3.y);
        aS.z += (x0.z + x1.z) + (x2.z + x3.z);
        aS.w += (x0.w + x1.w) + (x2.w + x3.w);
        aA.x += (a0.x + a1.x) + (a2.x + a3.x);
        aA.y += (a0.y + a1.y) + (a2.y + a3.y);
        aA.z += (a0.z + a1.z) + (a2.z + a3.z);
        aA.w += (a0.w + a1.w) + (a2.w + a3.w);
    }

    if (half == 1) {
        *(float4*)(&sS[nl][lane * 4]) = aS;
        *(float4*)(&sA[nl][lane * 4]) = aA;
    }
    __syncthreads();

    if (half == 0) {
        if (lane == 0) d_degf[n] = (float)deg;
        for (int j = groups * 4; j < cnt; j++) {
            int2 p = __ldg(bucket + j);
            float4 xv = ldg4(x + (size_t)p.y * D + lane * 4);
            float4 av = ldcs4(ea + (size_t)p.x * D + lane * 4);
            aS.x += xv.x; aS.y += xv.y; aS.z += xv.z; aS.w += xv.w;
            aA.x += av.x; aA.y += av.y; aA.z += av.z; aA.w += av.w;
        }
        if (deg > BUCKET) {
            int cnt_o = d_ovf_cnt;
            if (cnt_o > OVF_MAX) cnt_o = OVF_MAX;
            for (int i = 0; i < cnt_o; i++) {
                int3 v = d_ovf[i];
                if (v.x == n) {
                    float4 xv = ldg4(x + (size_t)v.z * D + lane * 4);
                    float4 av = ldg4(ea + (size_t)v.y * D + lane * 4);
                    aS.x += xv.x; aS.y += xv.y; aS.z += xv.z; aS.w += xv.w;
                    aA.x += av.x; aA.y += av.y; aA.z += av.z; aA.w += av.w;
                }
            }
        }
        float4 oS = *(float4*)(&sS[nl][lane * 4]);
        float4 oA = *(float4*)(&sA[nl][lane * 4]);
        aS.x += oS.x; aS.y += oS.y; aS.z += oS.z; aS.w += oS.w;
        aA.x += oA.x; aA.y += oA.y; aA.z += oA.z; aA.w += oA.w;
        *(float4*)(d_S + (size_t)n * D + lane * 4) = aS;
        *(float4*)(d_A + (size_t)n * D + lane * 4) = aA;
    }
}

// ---------------- K3: warp-MMA GEMM with register double-buffered staging ----------------
// Grid (157, 2). Block: 64 nodes x 64 outs, 256 threads (4m x 2n warps), warp tile m16n32.
// Prefetch chunk c+1 globals into registers while chunk c's MMAs run.
#define AROWB 144
#define ABUF  (64 * AROWB)
#define BBUF  (64 * AROWB)
__global__ void __launch_bounds__(256)
k_gemm_mma(const float* __restrict__ x,
           const float* __restrict__ b2,
           float* __restrict__ out) {
    extern __shared__ __align__(16) char sm[];
    char* Ahi = sm;
    char* Alo = sm + ABUF;
    char* Bhi = sm + 2 * ABUF;
    char* Blo = sm + 2 * ABUF + BBUF;
    uint32_t AhiU = smem_u32(Ahi), AloU = smem_u32(Alo);
    uint32_t BhiU = smem_u32(Bhi), BloU = smem_u32(Blo);

    int t = threadIdx.x;
    int wid = t >> 5, lane = t & 31;
    int wm = wid & 3, wn = wid >> 2;
    int n0 = blockIdx.x * 64;
    int obase = blockIdx.y * 64;

    int sub = lane >> 3, lr = lane & 7;
    uint32_t a_row = wm * 16 + ((sub & 1) << 3) + lr;
    uint32_t a_col = (uint32_t)((sub >> 1) << 4);
    uint32_t a_off = a_row * AROWB + a_col;
    uint32_t b_row = ((sub >> 1) << 3) + lr;
    uint32_t b_col = (uint32_t)((sub & 1) << 4);

    float acc[4][4];
#pragma unroll
    for (int i = 0; i < 4; i++)
#pragma unroll
        for (int j = 0; j < 4; j++) acc[i][j] = 0.f;

    // prefetch registers
    float4 pa[4];
    uint4  pbh[2], pbl[2];

    auto load_chunk = [&](int c) {
        int k0 = c * 64;
        int region = k0 >> 7;
        int kloc = k0 & 127;
        const float* base = (region == 0) ? d_S : (region == 1) ? d_A : x;
#pragma unroll
        for (int i = 0; i < 4; i++) {
            int id = t * 4 + i;
            int row = id >> 4, seg = id & 15;
            int nn = n0 + row;
            pa[i] = (nn < NUM_NODES) ? ldg4(base + (size_t)nn * D + kloc + seg * 4)
                                     : make_float4(0.f, 0.f, 0.f, 0.f);
        }
#pragma unroll
        for (int i = 0; i < 2; i++) {
            int id = t * 2 + i;
            int row = id >> 3, q = id & 7;
            pbh[i] = *(const uint4*)(d_MThi + (obase + row) * 512 + k0 + q * 8);
            pbl[i] = *(const uint4*)(d_MTlo + (obase + row) * 512 + k0 + q * 8);
        }
    };

    load_chunk(0);

    for (int c = 0; c < 8; c++) {
        int region = c >> 1;     // (c*64)>>7
        // ---- store staged registers to smem (convert A to hi/lo) ----
#pragma unroll
        for (int i = 0; i < 4; i++) {
            int id = t * 4 + i;
            int row = id >> 4, seg = id & 15;
            float4 v = pa[i];
            if (region == 3) {
                int nn = n0 + row;
                float dg = (nn < NUM_NODES) ? d_degf[nn] : 0.f;
                v.x *= dg; v.y *= dg; v.z *= dg; v.w *= dg;
            }
            uint2 HI, LO;
            split2(v.x, v.y, HI.x, LO.x);
            split2(v.z, v.w, HI.y, LO.y);
            *(uint2*)(Ahi + row * AROWB + seg * 8) = HI;
            *(uint2*)(Alo + row * AROWB + seg * 8) = LO;
        }
#pragma unroll
        for (int i = 0; i < 2; i++) {
            int id = t * 2 + i;
            int row = id >> 3, q = id & 7;
            *(uint4*)(Bhi + row * AROWB + q * 16) = pbh[i];
            *(uint4*)(Blo + row * AROWB + q * 16) = pbl[i];
        }
        __syncthreads();

        // ---- issue next chunk's global loads (hidden under the MMA loop) ----
        if (c < 7) load_chunk(c + 1);

        // ---- mma loop ----
#pragma unroll
        for (int s = 0; s < 4; s++) {
            uint32_t ah0, ah1, ah2, ah3, al0, al1, al2, al3;
            ldm_x4(ah0, ah1, ah2, ah3, AhiU + a_off + s * 32);
            ldm_x4(al0, al1, al2, al3, AloU + a_off + s * 32);
#pragma unroll
            for (int ntp = 0; ntp < 2; ntp++) {
                uint32_t boff = (wn * 32 + ntp * 16 + b_row) * AROWB + b_col + s * 32;
                uint32_t bh0, bh1, bh2, bh3, bl0, bl1, bl2, bl3;
                ldm_x4(bh0, bh1, bh2, bh3, BhiU + boff);
                ldm_x4(bl0, bl1, bl2, bl3, BloU + boff);
                mma16816(acc[ntp * 2 + 0], ah0, ah1, ah2, ah3, bh0, bh1);
                mma16816(acc[ntp * 2 + 0], ah0, ah1, ah2, ah3, bl0, bl1);
                mma16816(acc[ntp * 2 + 0], al0, al1, al2, al3, bh0, bh1);
                mma16816(acc[ntp * 2 + 1], ah0, ah1, ah2, ah3, bh2, bh3);
                mma16816(acc[ntp * 2 + 1], ah0, ah1, ah2, ah3, bl2, bl3);
                mma16816(acc[ntp * 2 + 1], al0, al1, al2, al3, bh2, bh3);
            }
        }
        __syncthreads();
    }

    int gid = lane >> 2, tig = lane & 3;
    int row0 = n0 + wm * 16 + gid;
    int row1 = row0 + 8;
    float dg0 = (row0 < NUM_NODES) ? d_degf[row0] : 0.f;
    float dg1 = (row1 < NUM_NODES) ? d_degf[row1] : 0.f;
#pragma unroll
    for (int nt = 0; nt < 4; nt++) {
        int col = obase + wn * 32 + nt * 8 + tig * 2;
        float c0 = d_cvec[col], c1 = d_cvec[col + 1];
        float z0 = b2[col], z1 = b2[col + 1];
        if (row0 < NUM_NODES) {
            float2 v = make_float2(acc[nt][0] + dg0 * c0 + z0,
                                   acc[nt][1] + dg0 * c1 + z1);
            *(float2*)(out + (size_t)row0 * D + col) = v;
        }
        if (row1 < NUM_NODES) {
            float2 v = make_float2(acc[nt][2] + dg1 * c0 + z0,
                                   acc[nt][3] + dg1 * c1 + z1);
            *(float2*)(out + (size_t)row1 * D + col) = v;
        }
    }
}

// ---------------- launch ----------------
extern "C" void kernel_launch(void* const* d_in, const int* in_sizes, int n_in,
                              void* d_out, int out_size) {
    const float* x  = (const float*)d_in[0];
    const void*  ei = d_in[1];
    const float* ea = (const float*)d_in[2];
    const float* W1 = (const float*)d_in[3];
    const float* b1 = (const float*)d_in[4];
    const float* W2 = (const float*)d_in[5];
    const float* b2 = (const float*)d_in[6];
    float* out = (float*)d_out;

    const int SMEM = 2 * ABUF + 2 * BBUF;   // 36864 B
    static bool attr_set = false;
    if (!attr_set) {
        cudaFuncSetAttribute(k_gemm_mma, cudaFuncAttributeMaxDynamicSharedMemorySize, SMEM);
        attr_set = true;
    }

    k_setup<<<592, 128>>>(W1, b1, W2, (const int*)ei);
    k_scatter<<<(N_EDGES + 255) / 256, 256>>>(ei);
    k_agg<<<(NUM_NODES + 3) / 4, 256>>>(x, ea);
    dim3 gg((NUM_NODES + 63) / 64, 2);
    k_gemm_mma<<<gg, 256, SMEM>>>(x, b2, out);
}

// round 15
// speedup vs baseline: 1.0829x; 1.0829x over previous
#include <cuda_runtime.h>
#include <cuda_bf16.h>
#include <cstdint>

#define NUM_NODES 10000
#define N_EDGES   640000
#define D         128
#define BUCKET    128
#define OVF_MAX   4096

// ---------------- device scratch ----------------
__device__ float d_S[NUM_NODES * D];
__device__ float d_A[NUM_NODES * D];
__device__ int   d_cur[NUM_NODES];
__device__ float d_degf[NUM_NODES];
__device__ int2  d_perm2[NUM_NODES * BUCKET];
__device__ int3  d_ovf[OVF_MAX];
__device__ int   d_ovf_cnt;
__device__ __nv_bfloat16 d_MThi[128 * 512];
__device__ __nv_bfloat16 d_MTlo[128 * 512];
__device__ float d_cvec[D];
__device__ int   d_is64;

// ---------------- helpers ----------------
__device__ __forceinline__ int load_idx(const void* ei, int which, int e, int is64) {
    if (is64) {
        const long long* p = (const long long*)ei;
        return (int)__ldg(p + (size_t)which * N_EDGES + e);
    } else {
        const int* p = (const int*)ei;
        return __ldg(p + (size_t)which * N_EDGES + e);
    }
}
__device__ __forceinline__ float4 ldg4(const float* p)  { return __ldg((const float4*)p); }
__device__ __forceinline__ float4 ldcs4(const float* p) { return __ldcs((const float4*)p); }

__device__ __forceinline__ uint32_t smem_u32(const void* p) {
    uint32_t a;
    asm("{ .reg .u64 t; cvta.to.shared.u64 t, %1; cvt.u32.u64 %0, t; }" : "=r"(a) : "l"(p));
    return a;
}

__device__ __forceinline__ void split2(float a, float b, uint32_t& hi, uint32_t& lo) {
    __nv_bfloat162 h = __floats2bfloat162_rn(a, b);
    float2 hf = __bfloat1622float2(h);
    __nv_bfloat162 l = __floats2bfloat162_rn(a - hf.x, b - hf.y);
    hi = *reinterpret_cast<uint32_t*>(&h);
    lo = *reinterpret_cast<uint32_t*>(&l);
}

__device__ __forceinline__ void ldm_x4(uint32_t& r0, uint32_t& r1, uint32_t& r2, uint32_t& r3,
                                       uint32_t addr) {
    asm volatile("ldmatrix.sync.aligned.m8n8.x4.shared.b16 {%0,%1,%2,%3}, [%4];"
                 : "=r"(r0), "=r"(r1), "=r"(r2), "=r"(r3) : "r"(addr));
}
__device__ __forceinline__ void mma16816(float* c,
                                         uint32_t a0, uint32_t a1, uint32_t a2, uint32_t a3,
                                         uint32_t b0, uint32_t b1) {
    asm volatile(
        "mma.sync.aligned.m16n8k16.row.col.f32.bf16.bf16.f32 "
        "{%0,%1,%2,%3}, {%4,%5,%6,%7}, {%8,%9}, {%0,%1,%2,%3};"
        : "+f"(c[0]), "+f"(c[1]), "+f"(c[2]), "+f"(c[3])
        : "r"(a0), "r"(a1), "r"(a2), "r"(a3), "r"(b0), "r"(b1));
}

// ---------------- K0: setup ----------------
__global__ void k_setup(const float* __restrict__ W1,
                        const float* __restrict__ b1,
                        const float* __restrict__ W2,
                        const int*   __restrict__ ei_words) {
    int r = blockIdx.x, o = threadIdx.x;
    if (r >= 512) {
        if (r == 512) {
            int w = ei_words[2 * o + 1];
            int any = __syncthreads_or(w != 0);
            if (o == 0) { d_is64 = (any == 0) ? 1 : 0; d_ovf_cnt = 0; }
        } else {
            int i = (r - 513) * 128 + o;
            if (i < NUM_NODES) d_cur[i] = 0;
        }
        return;
    }
    __shared__ float row[D];
    float v;
    if (r >= 256 && r < 384) {
        v = W2[(128 + (r - 256)) * D + o];
    } else {
        int w1row = (r < 128) ? r : (r < 256) ? (256 + (r - 128)) : (128 + (r - 384));
        row[o] = W1[w1row * D + o];
        __syncthreads();
        float acc = 0.f;
#pragma unroll 8
        for (int h = 0; h < D; h++) acc += row[h] * __ldg(W2 + h * D + o);
        v = acc;
        if (r == 0) {
            __syncthreads();
            row[o] = b1[o];
            __syncthreads();
            float c = 0.f;
#pragma unroll 8
            for (int h = 0; h < D; h++) c += row[h] * __ldg(W2 + h * D + o);
            d_cvec[o] = c;
        }
    }
    __nv_bfloat16 hi = __float2bfloat16_rn(v);
    d_MThi[o * 512 + r] = hi;
    d_MTlo[o * 512 + r] = __float2bfloat16_rn(v - __bfloat162float(hi));
}

// ---------------- K1: single-pass bucket scatter (R10 form) ----------------
__global__ void k_scatter(const void* ei) {
    int is64 = d_is64;
    int e = blockIdx.x * blockDim.x + threadIdx.x;
    if (e >= N_EDGES) return;
    int dst = load_idx(ei, 1, e, is64);
    int src = load_idx(ei, 0, e, is64);
    int pos = atomicAdd(&d_cur[dst], 1);
    if (pos < BUCKET) {
        d_perm2[(dst << 7) + pos] = make_int2(e, src);
    } else {
        int o = atomicAdd(&d_ovf_cnt, 1);
        if (o < OVF_MAX) d_ovf[o] = make_int3(dst, e, src);
    }
}

// ---------------- K2: segment sums (R10 form: one warp per node, plain unroll-4) ----------------
__global__ void k_agg(const float* __restrict__ x, const float* __restrict__ ea) {
    int n = blockIdx.x * 4 + (threadIdx.x >> 5);
    if (n >= NUM_NODES) return;
    int lane = threadIdx.x & 31;
    int deg = d_cur[n];
    if (lane == 0) d_degf[n] = (float)deg;
    int cnt = min(deg, BUCKET);
    const int2* bucket = d_perm2 + ((size_t)n << 7);

    float4 aS = make_float4(0.f, 0.f, 0.f, 0.f);
    float4 aA = make_float4(0.f, 0.f, 0.f, 0.f);

    int j = 0;
    for (; j + 4 <= cnt; j += 4) {
        int2 p0 = __ldg(bucket + j + 0);
        int2 p1 = __ldg(bucket + j + 1);
        int2 p2 = __ldg(bucket + j + 2);
        int2 p3 = __ldg(bucket + j + 3);
        float4 x0 = ldg4(x + (size_t)p0.y * D + lane * 4);
        float4 x1 = ldg4(x + (size_t)p1.y * D + lane * 4);
        float4 x2 = ldg4(x + (size_t)p2.y * D + lane * 4);
        float4 x3 = ldg4(x + (size_t)p3.y * D + lane * 4);
        float4 a0 = ldcs4(ea + (size_t)p0.x * D + lane * 4);
        float4 a1 = ldcs4(ea + (size_t)p1.x * D + lane * 4);
        float4 a2 = ldcs4(ea + (size_t)p2.x * D + lane * 4);
        float4 a3 = ldcs4(ea + (size_t)p3.x * D + lane * 4);
        aS.x += (x0.x + x1.x) + (x2.x + x3.x);
        aS.y += (x0.y + x1.y) + (x2.y + x3.y);
        aS.z += (x0.z + x1.z) + (x2.z + x3.z);
        aS.w += (x0.w + x1.w) + (x2.w + x3.w);
        aA.x += (a0.x + a1.x) + (a2.x + a3.x);
        aA.y += (a0.y + a1.y) + (a2.y + a3.y);
        aA.z += (a0.z + a1.z) + (a2.z + a3.z);
        aA.w += (a0.w + a1.w) + (a2.w + a3.w);
    }
    for (; j < cnt; j++) {
        int2 p = __ldg(bucket + j);
        float4 xv = ldg4(x + (size_t)p.y * D + lane * 4);
        float4 av = ldcs4(ea + (size_t)p.x * D + lane * 4);
        aS.x += xv.x; aS.y += xv.y; aS.z += xv.z; aS.w += xv.w;
        aA.x += av.x; aA.y += av.y; aA.z += av.z; aA.w += av.w;
    }

    if (deg > BUCKET) {
        int cnt_o = d_ovf_cnt;
        if (cnt_o > OVF_MAX) cnt_o = OVF_MAX;
        for (int i = 0; i < cnt_o; i++) {
            int3 v = d_ovf[i];
            if (v.x == n) {
                float4 xv = ldg4(x + (size_t)v.z * D + lane * 4);
                float4 av = ldg4(ea + (size_t)v.y * D + lane * 4);
                aS.x += xv.x; aS.y += xv.y; aS.z += xv.z; aS.w += xv.w;
                aA.x += av.x; aA.y += av.y; aA.z += av.z; aA.w += av.w;
            }
        }
    }

    *(float4*)(d_S + (size_t)n * D + lane * 4) = aS;
    *(float4*)(d_A + (size_t)n * D + lane * 4) = aA;
}

// ---------------- K3: warp-MMA GEMM (R11/R13 exact: grid (157,2), 64x64 tile, m16n32) ----
#define AROWB 144
#define ABUF  (64 * AROWB)
#define BBUF  (64 * AROWB)
__global__ void __launch_bounds__(256)
k_gemm_mma(const float* __restrict__ x,
           const float* __restrict__ b2,
           float* __restrict__ out) {
    extern __shared__ __align__(16) char sm[];
    char* Ahi = sm;
    char* Alo = sm + ABUF;
    char* Bhi = sm + 2 * ABUF;
    char* Blo = sm + 2 * ABUF + BBUF;
    uint32_t AhiU = smem_u32(Ahi), AloU = smem_u32(Alo);
    uint32_t BhiU = smem_u32(Bhi), BloU = smem_u32(Blo);

    int t = threadIdx.x;
    int wid = t >> 5, lane = t & 31;
    int wm = wid & 3, wn = wid >> 2;
    int n0 = blockIdx.x * 64;
    int obase = blockIdx.y * 64;

    int sub = lane >> 3, lr = lane & 7;
    uint32_t a_row = wm * 16 + ((sub & 1) << 3) + lr;
    uint32_t a_col = (uint32_t)((sub >> 1) << 4);
    uint32_t a_off = a_row * AROWB + a_col;
    uint32_t b_row = ((sub >> 1) << 3) + lr;
    uint32_t b_col = (uint32_t)((sub & 1) << 4);

    float acc[4][4];
#pragma unroll
    for (int i = 0; i < 4; i++)
#pragma unroll
        for (int j = 0; j < 4; j++) acc[i][j] = 0.f;

    for (int c = 0; c < 8; c++) {
        int k0 = c * 64;
        int region = k0 >> 7;
        int kloc = k0 & 127;
        const float* base = (region == 0) ? d_S : (region == 1) ? d_A : x;

#pragma unroll
        for (int i = 0; i < 4; i++) {
            int id = t * 4 + i;
            int row = id >> 4, seg = id & 15;
            int nn = n0 + row;
            float4 v = make_float4(0.f, 0.f, 0.f, 0.f);
            if (nn < NUM_NODES) {
                v = ldg4(base + (size_t)nn * D + kloc + seg * 4);
                if (region == 3) {
                    float dg = d_degf[nn];
                    v.x *= dg; v.y *= dg; v.z *= dg; v.w *= dg;
                }
            }
            uint2 HI, LO;
            split2(v.x, v.y, HI.x, LO.x);
            split2(v.z, v.w, HI.y, LO.y);
            *(uint2*)(Ahi + row * AROWB + seg * 8) = HI;
            *(uint2*)(Alo + row * AROWB + seg * 8) = LO;
        }
#pragma unroll
        for (int i = 0; i < 2; i++) {
            int id = t * 2 + i;
            int row = id >> 3, q = id & 7;
            *(uint4*)(Bhi + row * AROWB + q * 16) =
                *(const uint4*)(d_MThi + (obase + row) * 512 + k0 + q * 8);
            *(uint4*)(Blo + row * AROWB + q * 16) =
                *(const uint4*)(d_MTlo + (obase + row) * 512 + k0 + q * 8);
        }
        __syncthreads();

#pragma unroll
        for (int s = 0; s < 4; s++) {
            uint32_t ah0, ah1, ah2, ah3, al0, al1, al2, al3;
            ldm_x4(ah0, ah1, ah2, ah3, AhiU + a_off + s * 32);
            ldm_x4(al0, al1, al2, al3, AloU + a_off + s * 32);
#pragma unroll
            for (int ntp = 0; ntp < 2; ntp++) {
                uint32_t boff = (wn * 32 + ntp * 16 + b_row) * AROWB + b_col + s * 32;
                uint32_t bh0, bh1, bh2, bh3, bl0, bl1, bl2, bl3;
                ldm_x4(bh0, bh1, bh2, bh3, BhiU + boff);
                ldm_x4(bl0, bl1, bl2, bl3, BloU + boff);
                mma16816(acc[ntp * 2 + 0], ah0, ah1, ah2, ah3, bh0, bh1);
                mma16816(acc[ntp * 2 + 0], ah0, ah1, ah2, ah3, bl0, bl1);
                mma16816(acc[ntp * 2 + 0], al0, al1, al2, al3, bh0, bh1);
                mma16816(acc[ntp * 2 + 1], ah0, ah1, ah2, ah3, bh2, bh3);
                mma16816(acc[ntp * 2 + 1], ah0, ah1, ah2, ah3, bl2, bl3);
                mma16816(acc[ntp * 2 + 1], al0, al1, al2, al3, bh2, bh3);
            }
        }
        __syncthreads();
    }

    int gid = lane >> 2, tig = lane & 3;
    int row0 = n0 + wm * 16 + gid;
    int row1 = row0 + 8;
    float dg0 = (row0 < NUM_NODES) ? d_degf[row0] : 0.f;
    float dg1 = (row1 < NUM_NODES) ? d_degf[row1] : 0.f;
#pragma unroll
    for (int nt = 0; nt < 4; nt++) {
        int col = obase + wn * 32 + nt * 8 + tig * 2;
        float c0 = d_cvec[col], c1 = d_cvec[col + 1];
        float z0 = b2[col], z1 = b2[col + 1];
        if (row0 < NUM_NODES) {
            float2 v = make_float2(acc[nt][0] + dg0 * c0 + z0,
                                   acc[nt][1] + dg0 * c1 + z1);
            *(float2*)(out + (size_t)row0 * D + col) = v;
        }
        if (row1 < NUM_NODES) {
            float2 v = make_float2(acc[nt][2] + dg1 * c0 + z0,
                                   acc[nt][3] + dg1 * c1 + z1);
            *(float2*)(out + (size_t)row1 * D + col) = v;
        }
    }
}

// ---------------- launch ----------------
extern "C" void kernel_launch(void* const* d_in, const int* in_sizes, int n_in,
                              void* d_out, int out_size) {
    const float* x  = (const float*)d_in[0];
    const void*  ei = d_in[1];
    const float* ea = (const float*)d_in[2];
    const float* W1 = (const float*)d_in[3];
    const float* b1 = (const float*)d_in[4];
    const float* W2 = (const float*)d_in[5];
    const float* b2 = (const float*)d_in[6];
    float* out = (float*)d_out;

    const int SMEM = 2 * ABUF + 2 * BBUF;   // 36864 B
    static bool attr_set = false;
    if (!attr_set) {
        cudaFuncSetAttribute(k_gemm_mma, cudaFuncAttributeMaxDynamicSharedMemorySize, SMEM);
        attr_set = true;
    }

    k_setup<<<592, 128>>>(W1, b1, W2, (const int*)ei);
    k_scatter<<<(N_EDGES + 255) / 256, 256>>>(ei);
    k_agg<<<(NUM_NODES + 3) / 4, 128>>>(x, ea);
    dim3 gg((NUM_NODES + 63) / 64, 2);
    k_gemm_mma<<<gg, 256, SMEM>>>(x, b2, out);
}

// round 16
// speedup vs baseline: 1.1154x; 1.0299x over previous
#include <cuda_runtime.h>
#include <cuda_bf16.h>
#include <cstdint>

#define NUM_NODES 10000
#define N_EDGES   640000
#define D         128
#define BUCKET    128
#define OVF_MAX   4096
#define NB_FUSE   256   // leading blocks of k_scatfuse that do weight fusion

// ---------------- device scratch ----------------
__device__ float d_S[NUM_NODES * D];
__device__ float d_A[NUM_NODES * D];
__device__ int   d_cur[NUM_NODES];           // zero at load; re-zeroed by k_gemm each run
__device__ float d_degf[NUM_NODES];
__device__ int2  d_perm2[NUM_NODES * BUCKET];
__device__ int3  d_ovf[OVF_MAX];
__device__ int   d_ovf_cnt;                  // zero at load; re-zeroed by k_gemm each run
__device__ __nv_bfloat16 d_MThi[128 * 512];
__device__ __nv_bfloat16 d_MTlo[128 * 512];
__device__ float d_cvec[D];

// ---------------- helpers ----------------
__device__ __forceinline__ int load_idx(const void* ei, int which, int e, int is64) {
    if (is64) {
        const long long* p = (const long long*)ei;
        return (int)__ldg(p + (size_t)which * N_EDGES + e);
    } else {
        const int* p = (const int*)ei;
        return __ldg(p + (size_t)which * N_EDGES + e);
    }
}
__device__ __forceinline__ float4 ldg4(const float* p)  { return __ldg((const float4*)p); }
__device__ __forceinline__ float4 ldcs4(const float* p) { return __ldcs((const float4*)p); }

__device__ __forceinline__ uint32_t smem_u32(const void* p) {
    uint32_t a;
    asm("{ .reg .u64 t; cvta.to.shared.u64 t, %1; cvt.u32.u64 %0, t; }" : "=r"(a) : "l"(p));
    return a;
}

__device__ __forceinline__ void split2(float a, float b, uint32_t& hi, uint32_t& lo) {
    __nv_bfloat162 h = __floats2bfloat162_rn(a, b);
    float2 hf = __bfloat1622float2(h);
    __nv_bfloat162 l = __floats2bfloat162_rn(a - hf.x, b - hf.y);
    hi = *reinterpret_cast<uint32_t*>(&h);
    lo = *reinterpret_cast<uint32_t*>(&l);
}

__device__ __forceinline__ void ldm_x4(uint32_t& r0, uint32_t& r1, uint32_t& r2, uint32_t& r3,
                                       uint32_t addr) {
    asm volatile("ldmatrix.sync.aligned.m8n8.x4.shared.b16 {%0,%1,%2,%3}, [%4];"
                 : "=r"(r0), "=r"(r1), "=r"(r2), "=r"(r3) : "r"(addr));
}
__device__ __forceinline__ void mma16816(float* c,
                                         uint32_t a0, uint32_t a1, uint32_t a2, uint32_t a3,
                                         uint32_t b0, uint32_t b1) {
    asm volatile(
        "mma.sync.aligned.m16n8k16.row.col.f32.bf16.bf16.f32 "
        "{%0,%1,%2,%3}, {%4,%5,%6,%7}, {%8,%9}, {%0,%1,%2,%3};"
        : "+f"(c[0]), "+f"(c[1]), "+f"(c[2]), "+f"(c[3])
        : "r"(a0), "r"(a1), "r"(a2), "r"(a3), "r"(b0), "r"(b1));
}

// ---------------- K0: fused scatter + weight fusion (one launch, overlapped) ----------------
// Blocks [0, NB_FUSE): weight fusion, 2 k-rows per block (256 threads = 2 halves of 128).
// Blocks [NB_FUSE, ...): bucket scatter with inline per-block dtype probe.
// Requires d_cur == 0 and d_ovf_cnt == 0 on entry (static init / re-zeroed by k_gemm).
__global__ void __launch_bounds__(256)
k_scatfuse(const float* __restrict__ W1,
           const float* __restrict__ b1,
           const float* __restrict__ W2,
           const void* ei) {
    int b = blockIdx.x;
    int tid = threadIdx.x;

    if (b < NB_FUSE) {
        // ---- weight fusion: rows r = 2b + half ----
        __shared__ float rowbuf[2][D];
        int half = tid >> 7;
        int o = tid & 127;
        int r = b * 2 + half;
        // Mf rows: [0,128)=W1a@W2a (S)  [128,256)=W1c@W2a (A)  [256,384)=W2b (x)  [384,512)=W1b@W2a (deg*x)
        bool is_copy = (r >= 256 && r < 384);
        int w1row = (r < 128) ? r : (r < 256) ? (256 + (r - 128)) : (128 + (r - 384));
        rowbuf[half][o] = is_copy ? 0.f : W1[w1row * D + o];
        __syncthreads();
        float v;
        if (is_copy) {
            v = W2[(128 + (r - 256)) * D + o];
        } else {
            float acc = 0.f;
#pragma unroll 8
            for (int h = 0; h < D; h++) acc += rowbuf[half][h] * __ldg(W2 + h * D + o);
            v = acc;
        }
        __nv_bfloat16 hi = __float2bfloat16_rn(v);
        d_MThi[o * 512 + r] = hi;
        d_MTlo[o * 512 + r] = __float2bfloat16_rn(v - __bfloat162float(hi));

        // cvec = b1 @ W2a  (block 0 only; block-uniform branch)
        if (b == 0) {
            __syncthreads();
            if (half == 0) rowbuf[0][o] = b1[o];
            __syncthreads();
            if (half == 0) {
                float c = 0.f;
#pragma unroll 8
                for (int h = 0; h < D; h++) c += rowbuf[0][h] * __ldg(W2 + h * D + o);
                d_cvec[o] = c;
            }
        }
        return;
    }

    // ---- scatter with inline dtype probe ----
    // int64 indices < 10000 -> high word of every entry is 0. Probe 256 entries:
    // P(false positive with int32 data) = (1/10000)^256 ~ 0.
    int w = ((const int*)ei)[2 * tid + 1];
    int any = __syncthreads_or(w != 0);
    int is64 = (any == 0) ? 1 : 0;

    int e = (b - NB_FUSE) * 256 + tid;
    if (e >= N_EDGES) return;
    int dst = load_idx(ei, 1, e, is64);
    int src = load_idx(ei, 0, e, is64);
    int pos = atomicAdd(&d_cur[dst], 1);
    if (pos < BUCKET) {
        d_perm2[(dst << 7) + pos] = make_int2(e, src);
    } else {
        int o = atomicAdd(&d_ovf_cnt, 1);
        if (o < OVF_MAX) d_ovf[o] = make_int3(dst, e, src);
    }
}

// ---------------- K1: segment sums (R10/R15 known-good: one warp per node, unroll-4) ----------------
__global__ void k_agg(const float* __restrict__ x, const float* __restrict__ ea) {
    int n = blockIdx.x * 4 + (threadIdx.x >> 5);
    if (n >= NUM_NODES) return;
    int lane = threadIdx.x & 31;
    int deg = d_cur[n];
    if (lane == 0) d_degf[n] = (float)deg;
    int cnt = min(deg, BUCKET);
    const int2* bucket = d_perm2 + ((size_t)n << 7);

    float4 aS = make_float4(0.f, 0.f, 0.f, 0.f);
    float4 aA = make_float4(0.f, 0.f, 0.f, 0.f);

    int j = 0;
    for (; j + 4 <= cnt; j += 4) {
        int2 p0 = __ldg(bucket + j + 0);
        int2 p1 = __ldg(bucket + j + 1);
        int2 p2 = __ldg(bucket + j + 2);
        int2 p3 = __ldg(bucket + j + 3);
        float4 x0 = ldg4(x + (size_t)p0.y * D + lane * 4);
        float4 x1 = ldg4(x + (size_t)p1.y * D + lane * 4);
        float4 x2 = ldg4(x + (size_t)p2.y * D + lane * 4);
        float4 x3 = ldg4(x + (size_t)p3.y * D + lane * 4);
        float4 a0 = ldcs4(ea + (size_t)p0.x * D + lane * 4);
        float4 a1 = ldcs4(ea + (size_t)p1.x * D + lane * 4);
        float4 a2 = ldcs4(ea + (size_t)p2.x * D + lane * 4);
        float4 a3 = ldcs4(ea + (size_t)p3.x * D + lane * 4);
        aS.x += (x0.x + x1.x) + (x2.x + x3.x);
        aS.y += (x0.y + x1.y) + (x2.y + x3.y);
        aS.z += (x0.z + x1.z) + (x2.z + x3.z);
        aS.w += (x0.w + x1.w) + (x2.w + x3.w);
        aA.x += (a0.x + a1.x) + (a2.x + a3.x);
        aA.y += (a0.y + a1.y) + (a2.y + a3.y);
        aA.z += (a0.z + a1.z) + (a2.z + a3.z);
        aA.w += (a0.w + a1.w) + (a2.w + a3.w);
    }
    for (; j < cnt; j++) {
        int2 p = __ldg(bucket + j);
        float4 xv = ldg4(x + (size_t)p.y * D + lane * 4);
        float4 av = ldcs4(ea + (size_t)p.x * D + lane * 4);
        aS.x += xv.x; aS.y += xv.y; aS.z += xv.z; aS.w += xv.w;
        aA.x += av.x; aA.y += av.y; aA.z += av.z; aA.w += av.w;
    }

    if (deg > BUCKET) {
        int cnt_o = d_ovf_cnt;
        if (cnt_o > OVF_MAX) cnt_o = OVF_MAX;
        for (int i = 0; i < cnt_o; i++) {
            int3 v = d_ovf[i];
            if (v.x == n) {
                float4 xv = ldg4(x + (size_t)v.z * D + lane * 4);
                float4 av = ldg4(ea + (size_t)v.y * D + lane * 4);
                aS.x += xv.x; aS.y += xv.y; aS.z += xv.z; aS.w += xv.w;
                aA.x += av.x; aA.y += av.y; aA.z += av.z; aA.w += av.w;
            }
        }
    }

    *(float4*)(d_S + (size_t)n * D + lane * 4) = aS;
    *(float4*)(d_A + (size_t)n * D + lane * 4) = aA;
}

// ---------------- K2: warp-MMA GEMM (R15 exact) + counter re-zero for next run ----------------
#define AROWB 144
#define ABUF  (64 * AROWB)
#define BBUF  (64 * AROWB)
__global__ void __launch_bounds__(256)
k_gemm_mma(const float* __restrict__ x,
           const float* __restrict__ b2,
           float* __restrict__ out) {
    extern __shared__ __align__(16) char sm[];
    char* Ahi = sm;
    char* Alo = sm + ABUF;
    char* Bhi = sm + 2 * ABUF;
    char* Blo = sm + 2 * ABUF + BBUF;
    uint32_t AhiU = smem_u32(Ahi), AloU = smem_u32(Alo);
    uint32_t BhiU = smem_u32(Bhi), BloU = smem_u32(Blo);

    int t = threadIdx.x;
    int wid = t >> 5, lane = t & 31;
    int wm = wid & 3, wn = wid >> 2;
    int n0 = blockIdx.x * 64;
    int obase = blockIdx.y * 64;

    // self-clean counters for the NEXT kernel_launch invocation (agg already consumed them)
    {
        int bid = blockIdx.x + gridDim.x * blockIdx.y;   // 0..313
        if (t < 32) {
            int i = bid * 32 + t;
            if (i < NUM_NODES) d_cur[i] = 0;
        }
        if (bid == 0 && t == 32) d_ovf_cnt = 0;
    }

    int sub = lane >> 3, lr = lane & 7;
    uint32_t a_row = wm * 16 + ((sub & 1) << 3) + lr;
    uint32_t a_col = (uint32_t)((sub >> 1) << 4);
    uint32_t a_off = a_row * AROWB + a_col;
    uint32_t b_row = ((sub >> 1) << 3) + lr;
    uint32_t b_col = (uint32_t)((sub & 1) << 4);

    float acc[4][4];
#pragma unroll
    for (int i = 0; i < 4; i++)
#pragma unroll
        for (int j = 0; j < 4; j++) acc[i][j] = 0.f;

    for (int c = 0; c < 8; c++) {
        int k0 = c * 64;
        int region = k0 >> 7;
        int kloc = k0 & 127;
        const float* base = (region == 0) ? d_S : (region == 1) ? d_A : x;

#pragma unroll
        for (int i = 0; i < 4; i++) {
            int id = t * 4 + i;
            int row = id >> 4, seg = id & 15;
            int nn = n0 + row;
            float4 v = make_float4(0.f, 0.f, 0.f, 0.f);
            if (nn < NUM_NODES) {
                v = ldg4(base + (size_t)nn * D + kloc + seg * 4);
                if (region == 3) {
                    float dg = d_degf[nn];
                    v.x *= dg; v.y *= dg; v.z *= dg; v.w *= dg;
                }
            }
            uint2 HI, LO;
            split2(v.x, v.y, HI.x, LO.x);
            split2(v.z, v.w, HI.y, LO.y);
            *(uint2*)(Ahi + row * AROWB + seg * 8) = HI;
            *(uint2*)(Alo + row * AROWB + seg * 8) = LO;
        }
#pragma unroll
        for (int i = 0; i < 2; i++) {
            int id = t * 2 + i;
            int row = id >> 3, q = id & 7;
            *(uint4*)(Bhi + row * AROWB + q * 16) =
                *(const uint4*)(d_MThi + (obase + row) * 512 + k0 + q * 8);
            *(uint4*)(Blo + row * AROWB + q * 16) =
                *(const uint4*)(d_MTlo + (obase + row) * 512 + k0 + q * 8);
        }
        __syncthreads();

#pragma unroll
        for (int s = 0; s < 4; s++) {
            uint32_t ah0, ah1, ah2, ah3, al0, al1, al2, al3;
            ldm_x4(ah0, ah1, ah2, ah3, AhiU + a_off + s * 32);
            ldm_x4(al0, al1, al2, al3, AloU + a_off + s * 32);
#pragma unroll
            for (int ntp = 0; ntp < 2; ntp++) {
                uint32_t boff = (wn * 32 + ntp * 16 + b_row) * AROWB + b_col + s * 32;
                uint32_t bh0, bh1, bh2, bh3, bl0, bl1, bl2, bl3;
                ldm_x4(bh0, bh1, bh2, bh3, BhiU + boff);
                ldm_x4(bl0, bl1, bl2, bl3, BloU + boff);
                mma16816(acc[ntp * 2 + 0], ah0, ah1, ah2, ah3, bh0, bh1);
                mma16816(acc[ntp * 2 + 0], ah0, ah1, ah2, ah3, bl0, bl1);
                mma16816(acc[ntp * 2 + 0], al0, al1, al2, al3, bh0, bh1);
                mma16816(acc[ntp * 2 + 1], ah0, ah1, ah2, ah3, bh2, bh3);
                mma16816(acc[ntp * 2 + 1], ah0, ah1, ah2, ah3, bl2, bl3);
                mma16816(acc[ntp * 2 + 1], al0, al1, al2, al3, bh2, bh3);
            }
        }
        __syncthreads();
    }

    int gid = lane >> 2, tig = lane & 3;
    int row0 = n0 + wm * 16 + gid;
    int row1 = row0 + 8;
    float dg0 = (row0 < NUM_NODES) ? d_degf[row0] : 0.f;
    float dg1 = (row1 < NUM_NODES) ? d_degf[row1] : 0.f;
#pragma unroll
    for (int nt = 0; nt < 4; nt++) {
        int col = obase + wn * 32 + nt * 8 + tig * 2;
        float c0 = d_cvec[col], c1 = d_cvec[col + 1];
        float z0 = b2[col], z1 = b2[col + 1];
        if (row0 < NUM_NODES) {
            float2 v = make_float2(acc[nt][0] + dg0 * c0 + z0,
                                   acc[nt][1] + dg0 * c1 + z1);
            *(float2*)(out + (size_t)row0 * D + col) = v;
        }
        if (row1 < NUM_NODES) {
            float2 v = make_float2(acc[nt][2] + dg1 * c0 + z0,
                                   acc[nt][3] + dg1 * c1 + z1);
            *(float2*)(out + (size_t)row1 * D + col) = v;
        }
    }
}

// ---------------- launch ----------------
extern "C" void kernel_launch(void* const* d_in, const int* in_sizes, int n_in,
                              void* d_out, int out_size) {
    const float* x  = (const float*)d_in[0];
    const void*  ei = d_in[1];
    const float* ea = (const float*)d_in[2];
    const float* W1 = (const float*)d_in[3];
    const float* b1 = (const float*)d_in[4];
    const float* W2 = (const float*)d_in[5];
    const float* b2 = (const float*)d_in[6];
    float* out = (float*)d_out;

    const int SMEM = 2 * ABUF + 2 * BBUF;   // 36864 B
    static bool attr_set = false;
    if (!attr_set) {
        cudaFuncSetAttribute(k_gemm_mma, cudaFuncAttributeMaxDynamicSharedMemorySize, SMEM);
        attr_set = true;
    }

    k_scatfuse<<<NB_FUSE + (N_EDGES + 255) / 256, 256>>>(W1, b1, W2, ei);
    k_agg<<<(NUM_NODES + 3) / 4, 128>>>(x, ea);
    dim3 gg((NUM_NODES + 63) / 64, 2);
    k_gemm_mma<<<gg, 256, SMEM>>>(x, b2, out);
}